// round 15
// baseline (speedup 1.0000x reference)
#include <cuda_runtime.h>

// VanillaRNN, v13: two-kernel split.
//   K1: xproj[b][t][h] = x[b][t] @ W_hx^T  (flat, pipelined, 2048 CTAs)
//   K2: h = tanh(xproj_t + W_hh h)         (v8 engine, k=128 instead of 192)
// B=1024, T=512, I=64, H=128, O=10.
//
// K2 is the proven v8 chassis: 256 CTAs x 4 rows, 256 thr, 2 CTAs/SM,
// select-free butterfly (xor4/xor8/xor16 as pure keep+shfl), MUFU tanh,
// one barrier/step. k-domain shrinks 192 -> 128: FFMA2/thread/step 192->128,
// LDS.128 48->32. xp_t staged into smem by loader threads (prefetch t+1),
// added by the finalize lane before tanh.
//
// K1 uses the same engine mapping with k=64 and NO serial dependency:
// 4-row tiles, double-buffered x staging, direct STG of results. 2048
// uniform CTAs (~7 waves) -- no placement assumptions.

#define HDIM 128
#define IDIM 64
#define TSTEPS 512
#define BATCH 1024
#define ODIM 10

// 256 MB fp32 scratch for the x-projection
__device__ float g_xproj[(size_t)BATCH * TSTEPS * HDIM];

__device__ __forceinline__ unsigned long long ffma2(unsigned long long a,
                                                    unsigned long long b,
                                                    unsigned long long c) {
    unsigned long long d;
    asm("fma.rn.f32x2 %0, %1, %2, %3;" : "=l"(d) : "l"(a), "l"(b), "l"(c));
    return d;
}

__device__ __forceinline__ unsigned long long packf2(float lo, float hi) {
    return ((unsigned long long)__float_as_uint(hi) << 32) |
           (unsigned long long)__float_as_uint(lo);
}

__device__ __forceinline__ float sum2(unsigned long long a) {
    return __uint_as_float((unsigned)a) + __uint_as_float((unsigned)(a >> 32));
}

__device__ __forceinline__ float tanh_fast(float z) {
    float r;
    asm("tanh.approx.f32 %0, %1;" : "=f"(r) : "f"(z));
    return r;
}

// ============================================================================
// Kernel 1: xproj = x @ W_hx^T   (M = B*T = 524288, N = 128, K = 64)
// ============================================================================
// v8-style mapping, k=64: g = warp*4+(lane&3) col group (cols g+32*cg[c]);
// seg = lane>>2 in [0,8): 8-wide k-segment. Per 4-row tile per thread:
// 8 LDS.128, 64 FFMA2, 14 shfl, 2 STG. No inter-tile dependencies.

#define P_ROWSPT 4
#define P_TILES 64            // tiles per CTA -> 256 rows per CTA
#define P_GRID 2048           // 2048 * 256 = 524288 rows exactly
#define P_SEGF 8
#define P_SEGP 12             // seg bases 12s mod 32 banks: all distinct
#define P_RSTR 96             // 8*12

__global__ void __launch_bounds__(256, 2)
xproj_kernel(const float* __restrict__ x,
             const float* __restrict__ W_hx) {
    __shared__ __align__(16) float xs[2][P_ROWSPT][P_RSTR];

    const int tid  = threadIdx.x;
    const int lane = tid & 31;
    const int warp = tid >> 5;
    const int g    = warp * 4 + (lane & 3);
    const int seg  = lane >> 2;
    const int kb   = seg * P_SEGF;

    const int sb0 = seg & 1, sb1 = (seg >> 1) & 1, sb2 = (seg >> 2) & 1;

    int cg[4];
    cg[0] = 2 * sb2; cg[1] = 2 * sb2 + 1;
    cg[2] = 2 * (1 - sb2); cg[3] = 2 * (1 - sb2) + 1;

    // weights: 4 cols x 4 packed f32x2 (8 k each) = 32 floats
    unsigned long long w[4][4];
#pragma unroll
    for (int c = 0; c < 4; c++) {
        const int o = g + 32 * cg[c];
#pragma unroll
        for (int j = 0; j < 4; j++) {
            const int k0 = kb + 2 * j;
            w[c][j] = packf2(W_hx[o * IDIM + k0], W_hx[o * IDIM + k0 + 1]);
        }
    }

    const int rKA = sb1 + 2 * sb0;
    const int rSA = sb1 + 2 * (1 - sb0);
    const int rKB = (1 - sb1) + 2 * sb0;
    const int rSB = (1 - sb1) + 2 * (1 - sb0);
    const int segoff = seg * P_SEGP;
    const int oKA = rKA * P_RSTR + segoff;
    const int oSA = rSA * P_RSTR + segoff;
    const int oKB = rKB * P_RSTR + segoff;
    const int oSB = rSB * P_RSTR + segoff;

    const int mstar = 2 * sb0 + sb1;
    const int of0 = g + 32 * cg[0];
    const int of1 = of0 + 32;

    // loader mapping: tid<64, row xr, float4 chunk c4 (8%4==0: no straddle)
    const int xr  = (tid >> 4) & 3;
    const int c4  = (tid & 15) * 4;
    const int pc4 = (c4 / P_SEGF) * P_SEGP + (c4 % P_SEGF);
    const bool loader = (tid < 64);

    const size_t rbase = (size_t)blockIdx.x * (P_ROWSPT * P_TILES);

    // preload tile 0
    if (loader) {
        const float* src = x + (rbase + xr) * IDIM + c4;
        *(float4*)&xs[0][xr][pc4] = *(const float4*)src;
    }
    __syncthreads();

    int p = 0;
    for (int tile = 0; tile < P_TILES; tile++) {
        const size_t rt0 = rbase + (size_t)tile * P_ROWSPT;

        // prefetch next tile
        float4 xn;
        if (loader && tile + 1 < P_TILES) {
            const float* src = x + (rt0 + P_ROWSPT + xr) * IDIM + c4;
            xn = *(const float4*)src;
        }

        const float* base = &xs[p][0][0];

        // pair A
        float ra[4];
        {
            unsigned long long aK[4] = {0,0,0,0}, aS[4] = {0,0,0,0};
            const ulonglong2* pK = (const ulonglong2*)(base + oKA);
            const ulonglong2* pS = (const ulonglong2*)(base + oSA);
            ulonglong2 vK0 = pK[0], vK1 = pK[1];
            ulonglong2 vS0 = pS[0], vS1 = pS[1];
#pragma unroll
            for (int c = 0; c < 4; c++) {
                aK[c] = ffma2(vK0.x, w[c][0], aK[c]);
                aK[c] = ffma2(vK0.y, w[c][1], aK[c]);
                aK[c] = ffma2(vK1.x, w[c][2], aK[c]);
                aK[c] = ffma2(vK1.y, w[c][3], aK[c]);
                aS[c] = ffma2(vS0.x, w[c][0], aS[c]);
                aS[c] = ffma2(vS0.y, w[c][1], aS[c]);
                aS[c] = ffma2(vS1.x, w[c][2], aS[c]);
                aS[c] = ffma2(vS1.y, w[c][3], aS[c]);
            }
#pragma unroll
            for (int c = 0; c < 4; c++) {
                float k2 = sum2(aK[c]);
                float s2 = sum2(aS[c]);
                ra[c] = k2 + __shfl_xor_sync(0xffffffffu, s2, 4);
            }
        }
        // pair B
        float rb[4];
        {
            unsigned long long aK[4] = {0,0,0,0}, aS[4] = {0,0,0,0};
            const ulonglong2* pK = (const ulonglong2*)(base + oKB);
            const ulonglong2* pS = (const ulonglong2*)(base + oSB);
            ulonglong2 vK0 = pK[0], vK1 = pK[1];
            ulonglong2 vS0 = pS[0], vS1 = pS[1];
#pragma unroll
            for (int c = 0; c < 4; c++) {
                aK[c] = ffma2(vK0.x, w[c][0], aK[c]);
                aK[c] = ffma2(vK0.y, w[c][1], aK[c]);
                aK[c] = ffma2(vK1.x, w[c][2], aK[c]);
                aK[c] = ffma2(vK1.y, w[c][3], aK[c]);
                aS[c] = ffma2(vS0.x, w[c][0], aS[c]);
                aS[c] = ffma2(vS0.y, w[c][1], aS[c]);
                aS[c] = ffma2(vS1.x, w[c][2], aS[c]);
                aS[c] = ffma2(vS1.y, w[c][3], aS[c]);
            }
#pragma unroll
            for (int c = 0; c < 4; c++) {
                float k2 = sum2(aK[c]);
                float s2 = sum2(aS[c]);
                rb[c] = k2 + __shfl_xor_sync(0xffffffffu, s2, 4);
            }
        }

        float rc[4];
#pragma unroll
        for (int c = 0; c < 4; c++)
            rc[c] = ra[c] + __shfl_xor_sync(0xffffffffu, rb[c], 8);

        const float f0 = rc[0] + __shfl_xor_sync(0xffffffffu, rc[2], 16);
        const float f1 = rc[1] + __shfl_xor_sync(0xffffffffu, rc[3], 16);

        // direct store (all 512 floats of the tile covered exactly once)
        float* dst = g_xproj + (rt0 + mstar) * HDIM;
        dst[of0] = f0;
        dst[of1] = f1;

        if (loader && tile + 1 < P_TILES)
            *(float4*)&xs[p ^ 1][xr][pc4] = xn;
        __syncthreads();
        p ^= 1;
    }
}

// ============================================================================
// Kernel 2: recurrence  h = tanh(xp_t + W_hh h),  out = h_T @ W_ph^T + b_ph
// ============================================================================
// v8 chassis, k=128: seg = lane>>2 in [0,8) owns 16 h-k; segment stride 20
// floats (bases 20s mod 32: 0,20,8,28,16,4,24,12 -- conflict-free LDS.128).

#define ROWS 4
#define NTHREADS 256
#define SEGF 16
#define SEGP 20
#define RSTRIDE 160
#define XPSTR 132          // xps row stride (528B, 16B-aligned, bank-spread)
#define GRID 256

__device__ __forceinline__ int physh(int k) {
    return (k / SEGF) * SEGP + (k % SEGF);
}

// one row's 16-k slice (4 LDS.128) x 4 permuted cols = 32 FFMA2
__device__ __forceinline__ void row_acc_h(const float* __restrict__ rowseg,
                                          const unsigned long long w[4][8],
                                          float sv[4]) {
    const ulonglong2* pp = (const ulonglong2*)rowseg;
    ulonglong2 v0 = pp[0], v1 = pp[1], v2 = pp[2], v3 = pp[3];
    unsigned long long a0 = 0ull, a1 = 0ull, a2 = 0ull, a3 = 0ull;
    a0 = ffma2(v0.x, w[0][0], a0); a1 = ffma2(v0.x, w[1][0], a1);
    a2 = ffma2(v0.x, w[2][0], a2); a3 = ffma2(v0.x, w[3][0], a3);
    a0 = ffma2(v0.y, w[0][1], a0); a1 = ffma2(v0.y, w[1][1], a1);
    a2 = ffma2(v0.y, w[2][1], a2); a3 = ffma2(v0.y, w[3][1], a3);
    a0 = ffma2(v1.x, w[0][2], a0); a1 = ffma2(v1.x, w[1][2], a1);
    a2 = ffma2(v1.x, w[2][2], a2); a3 = ffma2(v1.x, w[3][2], a3);
    a0 = ffma2(v1.y, w[0][3], a0); a1 = ffma2(v1.y, w[1][3], a1);
    a2 = ffma2(v1.y, w[2][3], a2); a3 = ffma2(v1.y, w[3][3], a3);
    a0 = ffma2(v2.x, w[0][4], a0); a1 = ffma2(v2.x, w[1][4], a1);
    a2 = ffma2(v2.x, w[2][4], a2); a3 = ffma2(v2.x, w[3][4], a3);
    a0 = ffma2(v2.y, w[0][5], a0); a1 = ffma2(v2.y, w[1][5], a1);
    a2 = ffma2(v2.y, w[2][5], a2); a3 = ffma2(v2.y, w[3][5], a3);
    a0 = ffma2(v3.x, w[0][6], a0); a1 = ffma2(v3.x, w[1][6], a1);
    a2 = ffma2(v3.x, w[2][6], a2); a3 = ffma2(v3.x, w[3][6], a3);
    a0 = ffma2(v3.y, w[0][7], a0); a1 = ffma2(v3.y, w[1][7], a1);
    a2 = ffma2(v3.y, w[2][7], a2); a3 = ffma2(v3.y, w[3][7], a3);
    sv[0] = sum2(a0); sv[1] = sum2(a1); sv[2] = sum2(a2); sv[3] = sum2(a3);
}

__global__ void __launch_bounds__(NTHREADS, 2)
rnn_fused_kernel(const float* __restrict__ W_hh,
                 const float* __restrict__ b_hh,
                 const float* __restrict__ W_ph,
                 const float* __restrict__ b_ph,
                 float* __restrict__ out) {
    __shared__ __align__(16) float buf[2][ROWS][RSTRIDE];   // h state
    __shared__ __align__(16) float xps[2][ROWS][XPSTR];     // staged xproj

    const int tid  = threadIdx.x;
    const int lane = tid & 31;
    const int warp = tid >> 5;
    const int g    = warp * 4 + (lane & 3);
    const int seg  = lane >> 2;
    const int kb   = seg * SEGF;
    const int b0r  = blockIdx.x * ROWS;

    const int sb0 = seg & 1, sb1 = (seg >> 1) & 1, sb2 = (seg >> 2) & 1;

    int cg[4];
    cg[0] = 2 * sb2; cg[1] = 2 * sb2 + 1;
    cg[2] = 2 * (1 - sb2); cg[3] = 2 * (1 - sb2) + 1;

    // weights: W_hh only, 4 cols x 8 packed f32x2 (16 k each) = 64 floats
    unsigned long long w[4][8];
#pragma unroll
    for (int c = 0; c < 4; c++) {
        const int o = g + 32 * cg[c];
#pragma unroll
        for (int j = 0; j < 8; j++) {
            const int k0 = kb + 2 * j;
            w[c][j] = packf2(W_hh[o * HDIM + k0], W_hh[o * HDIM + k0 + 1]);
        }
    }

    const int rKA = sb1 + 2 * sb0;
    const int rSA = sb1 + 2 * (1 - sb0);
    const int rKB = (1 - sb1) + 2 * sb0;
    const int rSB = (1 - sb1) + 2 * (1 - sb0);
    const int segoff = seg * SEGP;
    const int oKA = rKA * RSTRIDE + segoff;
    const int oSA = rSA * RSTRIDE + segoff;
    const int oKB = rKB * RSTRIDE + segoff;
    const int oSB = rSB * RSTRIDE + segoff;

    const int mstar = 2 * sb0 + sb1;
    const int of0 = g + 32 * cg[0];
    const int of1 = of0 + 32;
    const float bb0 = b_hh[of0];
    const float bb1 = b_hh[of1];
    const int ph0 = physh(of0);
    const int ph1 = physh(of1);
    const int xq0 = mstar * XPSTR + of0;   // xp fetch offsets
    const int xq1 = mstar * XPSTR + of1;

    // zero h buffers
    for (int i = tid; i < 2 * ROWS * RSTRIDE; i += NTHREADS)
        ((float*)buf)[i] = 0.0f;

    // xp loader: tid<128, row xr = tid>>5, float4 chunk c4 = (tid&31)*4
    const int xr  = (tid >> 5) & 3;
    const int c4  = (tid & 31) * 4;
    const bool loader = (tid < 128);
    const float* xprow = g_xproj + ((size_t)(b0r + xr) * TSTEPS) * HDIM;

    if (loader)
        *(float4*)&xps[0][xr][c4] = *(const float4*)(xprow + c4);   // xp_0
    __syncthreads();

    int p = 0;
    for (int t = 0; t < TSTEPS; t++) {
        float4 xn;
        if (loader) {
            const int tn = (t + 1 < TSTEPS) ? t + 1 : TSTEPS - 1;
            xn = *(const float4*)(xprow + (size_t)tn * HDIM + c4);
        }

        // fetch this lane's xp pair early (independent of h chain)
        const float xp0 = xps[p][0][xq0];
        const float xp1 = xps[p][0][xq1];

        const float* base = &buf[p][0][0];

        float ra[4];
        {
            float aK[4], aS[4];
            row_acc_h(base + oKA, w, aK);
            row_acc_h(base + oSA, w, aS);
#pragma unroll
            for (int c = 0; c < 4; c++)
                ra[c] = aK[c] + __shfl_xor_sync(0xffffffffu, aS[c], 4);
        }
        float rb[4];
        {
            float aK[4], aS[4];
            row_acc_h(base + oKB, w, aK);
            row_acc_h(base + oSB, w, aS);
#pragma unroll
            for (int c = 0; c < 4; c++)
                rb[c] = aK[c] + __shfl_xor_sync(0xffffffffu, aS[c], 4);
        }

        float rc[4];
#pragma unroll
        for (int c = 0; c < 4; c++)
            rc[c] = ra[c] + __shfl_xor_sync(0xffffffffu, rb[c], 8);

        const float f0 = rc[0] + __shfl_xor_sync(0xffffffffu, rc[2], 16);
        const float f1 = rc[1] + __shfl_xor_sync(0xffffffffu, rc[3], 16);

        const int q = p ^ 1;
        buf[q][mstar][ph0] = tanh_fast(f0 + xp0 + bb0);
        buf[q][mstar][ph1] = tanh_fast(f1 + xp1 + bb1);

        if (loader) *(float4*)&xps[q][xr][c4] = xn;

        __syncthreads();
        p = q;
    }

    // final projection
    if (tid < ROWS * ODIM) {
        const int m = tid / ODIM;
        const int j = tid % ODIM;
        float s = b_ph[j];
#pragma unroll 4
        for (int k = 0; k < HDIM; k++)
            s += buf[p][m][physh(k)] * W_ph[j * HDIM + k];
        out[(size_t)(b0r + m) * ODIM + j] = s;
    }
}

extern "C" void kernel_launch(void* const* d_in, const int* in_sizes, int n_in,
                              void* d_out, int out_size) {
    const float* x    = (const float*)d_in[0];
    const float* W_hx = (const float*)d_in[1];
    const float* W_hh = (const float*)d_in[2];
    const float* b_hh = (const float*)d_in[3];
    const float* W_ph = (const float*)d_in[4];
    const float* b_ph = (const float*)d_in[5];
    float* out = (float*)d_out;

    xproj_kernel<<<P_GRID, 256>>>(x, W_hx);
    rnn_fused_kernel<<<GRID, NTHREADS>>>(W_hh, b_hh, W_ph, b_ph, out);
}